// round 1
// baseline (speedup 1.0000x reference)
#include <cuda_runtime.h>
#include <math.h>

// Shapes (fixed by the problem)
#define B_SZ   16
#define T_SEQ  1024
#define C_DIM  768
#define NH     12
#define DH     64
#define C3     2304       // 3*C
#define M_ROWS 16384      // B*T

// Scratch buffers (no cudaMalloc allowed)
__device__ float g_qkv[(size_t)M_ROWS * C3];   // [B*T, 3C]
__device__ float g_y[(size_t)M_ROWS * C_DIM];  // [B*T, C]

// ---------------------------------------------------------------------------
// SGEMM: C = A[M,K] @ B[K,N] + bias[N], all row-major.
// 128x128 block tile, BK=8, 256 threads, 8x8 per-thread micro-tile.
// M % 128 == 0, N % 128 == 0, K % 8 == 0 (true for both call sites).
// ---------------------------------------------------------------------------
#define BM 128
#define BN 128
#define BK 8

__global__ __launch_bounds__(256) void sgemm_bias(
    const float* __restrict__ A, const float* __restrict__ B,
    const float* __restrict__ bias, float* __restrict__ C,
    int M, int N, int K)
{
    __shared__ float As[BK][BM];
    __shared__ float Bs[BK][BN];

    const int tid = threadIdx.x;
    const int tx  = tid & 15;       // 0..15  -> 8 cols each
    const int ty  = tid >> 4;       // 0..15  -> 8 rows each

    const int aRow = tid >> 1;          // 0..127
    const int aCol = (tid & 1) * 4;     // 0 or 4
    const int bRow = tid >> 5;          // 0..7
    const int bCol = (tid & 31) * 4;    // 0..124

    const float* Ab = A + (size_t)blockIdx.y * BM * K;
    const float* Bb = B + (size_t)blockIdx.x * BN;

    float acc[8][8];
#pragma unroll
    for (int i = 0; i < 8; i++)
#pragma unroll
        for (int j = 0; j < 8; j++) acc[i][j] = 0.f;

    for (int k0 = 0; k0 < K; k0 += BK) {
        float4 av = *(const float4*)(Ab + (size_t)aRow * K + k0 + aCol);
        As[aCol + 0][aRow] = av.x;
        As[aCol + 1][aRow] = av.y;
        As[aCol + 2][aRow] = av.z;
        As[aCol + 3][aRow] = av.w;
        *(float4*)&Bs[bRow][bCol] =
            *(const float4*)(Bb + (size_t)(k0 + bRow) * N + bCol);
        __syncthreads();

#pragma unroll
        for (int k = 0; k < BK; k++) {
            float4 a0 = *(const float4*)&As[k][ty * 8];
            float4 a1 = *(const float4*)&As[k][ty * 8 + 4];
            float4 b0 = *(const float4*)&Bs[k][tx * 8];
            float4 b1 = *(const float4*)&Bs[k][tx * 8 + 4];
            float a[8] = {a0.x, a0.y, a0.z, a0.w, a1.x, a1.y, a1.z, a1.w};
            float b[8] = {b0.x, b0.y, b0.z, b0.w, b1.x, b1.y, b1.z, b1.w};
#pragma unroll
            for (int i = 0; i < 8; i++)
#pragma unroll
                for (int j = 0; j < 8; j++)
                    acc[i][j] = fmaf(a[i], b[j], acc[i][j]);
        }
        __syncthreads();
    }

    float* Cb = C + (size_t)blockIdx.y * BM * N + (size_t)blockIdx.x * BN;
    const float* biasb = bias + (size_t)blockIdx.x * BN;
#pragma unroll
    for (int i = 0; i < 8; i++) {
        int r = ty * 8 + i;
#pragma unroll
        for (int j = 0; j < 8; j += 4) {
            int c = tx * 8 + j;
            float4 v;
            v.x = acc[i][j + 0] + biasb[c + 0];
            v.y = acc[i][j + 1] + biasb[c + 1];
            v.z = acc[i][j + 2] + biasb[c + 2];
            v.w = acc[i][j + 3] + biasb[c + 3];
            *(float4*)(Cb + (size_t)r * N + c) = v;
        }
    }
}

// ---------------------------------------------------------------------------
// Flash-attention (fp32, causal). One block per (q_tile=64, head, batch).
// 256 threads. Q pre-scaled by 1/sqrt(D). Online softmax.
// Smem: Qs[d][r], Ks[d][j] (d-major for outer-product), Vs[j][d], Ps[r][j+pad].
// ---------------------------------------------------------------------------
__global__ __launch_bounds__(256) void attn_kernel(
    const float* __restrict__ qkv, float* __restrict__ y)
{
    extern __shared__ float sm[];
    float (*Qs)[64] = (float(*)[64])(sm);           // 4096 floats
    float (*Ks)[64] = (float(*)[64])(sm + 4096);    // 4096
    float (*Vs)[64] = (float(*)[64])(sm + 8192);    // 4096
    float (*Ps)[68] = (float(*)[68])(sm + 12288);   // 64*68 = 4352

    const int qt = blockIdx.x;   // 0..15
    const int h  = blockIdx.y;   // 0..11
    const int b  = blockIdx.z;   // 0..15
    const int q0 = qt * 64;

    const int tid = threadIdx.x;
    const int tx  = tid & 15;    // col group (4 cols)
    const int ty  = tid >> 4;    // row group (4 rows)

    // loader mapping: 4 threads per row, 16 contiguous floats each
    const int lr  = tid >> 2;          // 0..63
    const int ld0 = (tid & 3) << 4;    // 0,16,32,48

    // ---- load Q tile (transposed, pre-scaled) ----
    {
        const float* qb = qkv + ((size_t)(b * T_SEQ + q0 + lr)) * C3 + h * DH + ld0;
#pragma unroll
        for (int g = 0; g < 4; g++) {
            float4 v = *(const float4*)(qb + g * 4);
            int d = ld0 + g * 4;
            Qs[d + 0][lr] = v.x * 0.125f;
            Qs[d + 1][lr] = v.y * 0.125f;
            Qs[d + 2][lr] = v.z * 0.125f;
            Qs[d + 3][lr] = v.w * 0.125f;
        }
    }

    float m[4], l[4], o[4][4];
#pragma unroll
    for (int i = 0; i < 4; i++) {
        m[i] = -1e30f; l[i] = 0.f;
#pragma unroll
        for (int c = 0; c < 4; c++) o[i][c] = 0.f;
    }

    for (int k0 = 0; k0 <= q0; k0 += 64) {
        __syncthreads();   // protect Ks/Vs/Ps from previous iteration consumers

        // ---- load K (transposed) and V (row-major) tiles ----
        {
            const float* kb = qkv + ((size_t)(b * T_SEQ + k0 + lr)) * C3
                              + C_DIM + h * DH + ld0;
            const float* vb = qkv + ((size_t)(b * T_SEQ + k0 + lr)) * C3
                              + 2 * C_DIM + h * DH + ld0;
#pragma unroll
            for (int g = 0; g < 4; g++) {
                float4 kv = *(const float4*)(kb + g * 4);
                int d = ld0 + g * 4;
                Ks[d + 0][lr] = kv.x;
                Ks[d + 1][lr] = kv.y;
                Ks[d + 2][lr] = kv.z;
                Ks[d + 3][lr] = kv.w;
                *(float4*)&Vs[lr][d] = *(const float4*)(vb + g * 4);
            }
        }
        __syncthreads();

        // ---- S = Q @ K^T (4x4 per thread) ----
        float s[4][4];
#pragma unroll
        for (int i = 0; i < 4; i++)
#pragma unroll
            for (int j = 0; j < 4; j++) s[i][j] = 0.f;

#pragma unroll 8
        for (int d = 0; d < 64; d++) {
            float4 aq = *(const float4*)&Qs[d][ty * 4];
            float4 bk = *(const float4*)&Ks[d][tx * 4];
            float a[4] = {aq.x, aq.y, aq.z, aq.w};
            float bb[4] = {bk.x, bk.y, bk.z, bk.w};
#pragma unroll
            for (int i = 0; i < 4; i++)
#pragma unroll
                for (int j = 0; j < 4; j++)
                    s[i][j] = fmaf(a[i], bb[j], s[i][j]);
        }

        // ---- causal mask (only diagonal tile) ----
        if (k0 == q0) {
#pragma unroll
            for (int i = 0; i < 4; i++)
#pragma unroll
                for (int j = 0; j < 4; j++)
                    if (tx * 4 + j > ty * 4 + i) s[i][j] = -1e30f;
        }

        // ---- online softmax (row reductions across the 16-lane tx group) ----
#pragma unroll
        for (int i = 0; i < 4; i++) {
            float mx = fmaxf(fmaxf(s[i][0], s[i][1]), fmaxf(s[i][2], s[i][3]));
#pragma unroll
            for (int off = 1; off < 16; off <<= 1)
                mx = fmaxf(mx, __shfl_xor_sync(0xffffffffu, mx, off));
            float mn = fmaxf(m[i], mx);
            float f  = __expf(m[i] - mn);
            float p0 = __expf(s[i][0] - mn);
            float p1 = __expf(s[i][1] - mn);
            float p2 = __expf(s[i][2] - mn);
            float p3 = __expf(s[i][3] - mn);
            float rs = p0 + p1 + p2 + p3;
#pragma unroll
            for (int off = 1; off < 16; off <<= 1)
                rs += __shfl_xor_sync(0xffffffffu, rs, off);
            l[i] = l[i] * f + rs;
            m[i] = mn;
#pragma unroll
            for (int c = 0; c < 4; c++) o[i][c] *= f;
            *(float4*)&Ps[ty * 4 + i][tx * 4] = make_float4(p0, p1, p2, p3);
        }
        __syncthreads();

        // ---- O += P @ V ----
#pragma unroll 8
        for (int j = 0; j < 64; j++) {
            float4 v = *(const float4*)&Vs[j][tx * 4];
#pragma unroll
            for (int i = 0; i < 4; i++) {
                float a = Ps[ty * 4 + i][j];
                o[i][0] = fmaf(a, v.x, o[i][0]);
                o[i][1] = fmaf(a, v.y, o[i][1]);
                o[i][2] = fmaf(a, v.z, o[i][2]);
                o[i][3] = fmaf(a, v.w, o[i][3]);
            }
        }
    }

    // ---- normalize + write y[B,T,C] ----
#pragma unroll
    for (int i = 0; i < 4; i++) {
        float inv = 1.f / l[i];
        float4 v = make_float4(o[i][0] * inv, o[i][1] * inv,
                               o[i][2] * inv, o[i][3] * inv);
        size_t row = (size_t)(b * T_SEQ + q0 + ty * 4 + i);
        *(float4*)(y + row * C_DIM + h * DH + tx * 4) = v;
    }
}

// ---------------------------------------------------------------------------
extern "C" void kernel_launch(void* const* d_in, const int* in_sizes, int n_in,
                              void* d_out, int out_size)
{
    const float* x     = (const float*)d_in[0];
    const float* Wqkv  = (const float*)d_in[1];
    const float* bqkv  = (const float*)d_in[2];
    const float* Wproj = (const float*)d_in[3];
    const float* bproj = (const float*)d_in[4];
    float* out = (float*)d_out;

    float *qkv, *y;
    cudaGetSymbolAddress((void**)&qkv, g_qkv);
    cudaGetSymbolAddress((void**)&y, g_y);

    const int attn_smem = (4096 * 3 + 64 * 68) * sizeof(float);  // 66560 B
    cudaFuncSetAttribute(attn_kernel,
                         cudaFuncAttributeMaxDynamicSharedMemorySize, attn_smem);

    // 1) QKV projection
    sgemm_bias<<<dim3(C3 / BN, M_ROWS / BM), 256>>>(
        x, Wqkv, bqkv, qkv, M_ROWS, C3, C_DIM);

    // 2) causal attention
    attn_kernel<<<dim3(T_SEQ / 64, NH, B_SZ), 256, attn_smem>>>(qkv, y);

    // 3) output projection
    sgemm_bias<<<dim3(C_DIM / BN, M_ROWS / BM), 256>>>(
        y, Wproj, bproj, out, M_ROWS, C_DIM, C_DIM);
}

// round 2
// speedup vs baseline: 1.5582x; 1.5582x over previous
#include <cuda_runtime.h>
#include <math.h>
#include <stdint.h>

// Shapes (fixed by the problem)
#define B_SZ   16
#define T_SEQ  1024
#define C_DIM  768
#define NH     12
#define DH     64
#define C3     2304       // 3*C
#define M_ROWS 16384      // B*T

// Scratch buffers (no cudaMalloc allowed)
__device__ float g_qkv[(size_t)M_ROWS * C3];   // [B*T, 3C]
__device__ float g_y[(size_t)M_ROWS * C_DIM];  // [B*T, C]

// ---------------------------------------------------------------------------
// TF32 tensor-core GEMM: C = A[M,K] @ B[K,N] + bias[N], row-major.
// 128x128x32 CTA tile, 256 threads (8 warps, 2x4), warp tile 64x32,
// mma.sync.m16n8k8.tf32. M%128==0, N%128==0, K%32==0.
// ---------------------------------------------------------------------------
#define TBM 128
#define TBN 128
#define TBK 32
#define APAD 4     // As[m][TBK+4]  -> bank = (4*g + tg)     (conflict-free)
#define BPAD 8     // Bs[k][TBN+8]  -> bank = (8*tg + g)     (conflict-free)

__device__ __forceinline__ uint32_t f2tf32(float x) {
    uint32_t y;
    asm volatile("cvt.rna.tf32.f32 %0, %1;" : "=r"(y) : "f"(x));
    return y;
}

__device__ __forceinline__ void mma_tf32(float* c, const uint32_t* a, const uint32_t* b) {
    asm volatile(
        "mma.sync.aligned.m16n8k8.row.col.f32.tf32.tf32.f32 "
        "{%0,%1,%2,%3}, {%4,%5,%6,%7}, {%8,%9}, {%0,%1,%2,%3};"
        : "+f"(c[0]), "+f"(c[1]), "+f"(c[2]), "+f"(c[3])
        : "r"(a[0]), "r"(a[1]), "r"(a[2]), "r"(a[3]), "r"(b[0]), "r"(b[1]));
}

__global__ __launch_bounds__(256) void tf32_gemm_bias(
    const float* __restrict__ A, const float* __restrict__ B,
    const float* __restrict__ bias, float* __restrict__ C,
    int M, int N, int K)
{
    __shared__ uint32_t As[TBM][TBK + APAD];   // [m][k], tf32 bits
    __shared__ uint32_t Bs[TBK][TBN + BPAD];   // [k][n], tf32 bits

    const int tid  = threadIdx.x;
    const int wid  = tid >> 5;
    const int lane = tid & 31;
    const int wm   = wid & 1;        // warp row: 64 rows each
    const int wn   = wid >> 1;       // warp col: 32 cols each
    const int g    = lane >> 2;      // group id (0..7)
    const int tg   = lane & 3;       // thread-in-group (0..3)

    // A loader: row = tid>>1 (0..127), 16 floats at col (tid&1)*16
    const int ar = tid >> 1;
    const int ac = (tid & 1) * 16;
    // B loader: k = tid>>3 (0..31), 16 floats at col (tid&7)*16
    const int br = tid >> 3;
    const int bc = (tid & 7) * 16;

    const float* Ag = A + (size_t)(blockIdx.y * TBM + ar) * K + ac;
    const float* Bg = B + (size_t)br * N + blockIdx.x * TBN + bc;

    float acc[4][4][4];
#pragma unroll
    for (int mt = 0; mt < 4; mt++)
#pragma unroll
        for (int nt = 0; nt < 4; nt++)
#pragma unroll
            for (int c = 0; c < 4; c++) acc[mt][nt][c] = 0.f;

    float4 pa[4], pb[4];
    // prefetch tile 0
#pragma unroll
    for (int j = 0; j < 4; j++) {
        pa[j] = *(const float4*)(Ag + 4 * j);
        pb[j] = *(const float4*)(Bg + 4 * j);
    }
    // store tile 0 (convert to tf32)
#pragma unroll
    for (int j = 0; j < 4; j++) {
        uint32_t* as = &As[ar][ac + 4 * j];
        as[0] = f2tf32(pa[j].x); as[1] = f2tf32(pa[j].y);
        as[2] = f2tf32(pa[j].z); as[3] = f2tf32(pa[j].w);
        uint32_t* bs = &Bs[br][bc + 4 * j];
        bs[0] = f2tf32(pb[j].x); bs[1] = f2tf32(pb[j].y);
        bs[2] = f2tf32(pb[j].z); bs[3] = f2tf32(pb[j].w);
    }
    __syncthreads();

    for (int k0 = 0; k0 < K; k0 += TBK) {
        const bool has_next = (k0 + TBK) < K;
        if (has_next) {
#pragma unroll
            for (int j = 0; j < 4; j++) {
                pa[j] = *(const float4*)(Ag + (k0 + TBK) + 4 * j);
                pb[j] = *(const float4*)(Bg + (size_t)(k0 + TBK) * N + 4 * j);
            }
        }

#pragma unroll
        for (int ks = 0; ks < 4; ks++) {
            uint32_t af[4][4], bf[4][2];
#pragma unroll
            for (int mt = 0; mt < 4; mt++) {
                const int am = wm * 64 + mt * 16;
                const int kk = ks * 8 + tg;
                af[mt][0] = As[am + g    ][kk    ];
                af[mt][1] = As[am + g + 8][kk    ];
                af[mt][2] = As[am + g    ][kk + 4];
                af[mt][3] = As[am + g + 8][kk + 4];
            }
#pragma unroll
            for (int nt = 0; nt < 4; nt++) {
                const int bn = wn * 32 + nt * 8 + g;
                const int kk = ks * 8 + tg;
                bf[nt][0] = Bs[kk    ][bn];
                bf[nt][1] = Bs[kk + 4][bn];
            }
#pragma unroll
            for (int mt = 0; mt < 4; mt++)
#pragma unroll
                for (int nt = 0; nt < 4; nt++)
                    mma_tf32(acc[mt][nt], af[mt], bf[nt]);
        }

        __syncthreads();
        if (has_next) {
#pragma unroll
            for (int j = 0; j < 4; j++) {
                uint32_t* as = &As[ar][ac + 4 * j];
                as[0] = f2tf32(pa[j].x); as[1] = f2tf32(pa[j].y);
                as[2] = f2tf32(pa[j].z); as[3] = f2tf32(pa[j].w);
                uint32_t* bs = &Bs[br][bc + 4 * j];
                bs[0] = f2tf32(pb[j].x); bs[1] = f2tf32(pb[j].y);
                bs[2] = f2tf32(pb[j].z); bs[3] = f2tf32(pb[j].w);
            }
            __syncthreads();
        }
    }

    // epilogue: bias + store (c0,c1 at row, c2,c3 at row+8; cols 2tg, 2tg+1)
    const int crow0 = blockIdx.y * TBM + wm * 64;
    const int ccol0 = blockIdx.x * TBN + wn * 32;
#pragma unroll
    for (int mt = 0; mt < 4; mt++) {
#pragma unroll
        for (int nt = 0; nt < 4; nt++) {
            const int row = crow0 + mt * 16 + g;
            const int col = ccol0 + nt * 8 + 2 * tg;
            const float b0 = bias[col], b1 = bias[col + 1];
            float2 v0 = make_float2(acc[mt][nt][0] + b0, acc[mt][nt][1] + b1);
            float2 v1 = make_float2(acc[mt][nt][2] + b0, acc[mt][nt][3] + b1);
            *(float2*)(C + (size_t)row * N + col)       = v0;
            *(float2*)(C + (size_t)(row + 8) * N + col) = v1;
        }
    }
}

// ---------------------------------------------------------------------------
// Flash-attention (fp32, causal). One block per (q_tile=64, head, batch).
// 256 threads. Q pre-scaled by 1/sqrt(D). Online softmax.
// ---------------------------------------------------------------------------
__global__ __launch_bounds__(256) void attn_kernel(
    const float* __restrict__ qkv, float* __restrict__ y)
{
    extern __shared__ float sm[];
    float (*Qs)[64] = (float(*)[64])(sm);           // 4096 floats
    float (*Ks)[64] = (float(*)[64])(sm + 4096);    // 4096
    float (*Vs)[64] = (float(*)[64])(sm + 8192);    // 4096
    float (*Ps)[68] = (float(*)[68])(sm + 12288);   // 64*68 = 4352

    const int qt = blockIdx.x;   // 0..15
    const int h  = blockIdx.y;   // 0..11
    const int b  = blockIdx.z;   // 0..15
    const int q0 = qt * 64;

    const int tid = threadIdx.x;
    const int tx  = tid & 15;    // col group (4 cols)
    const int ty  = tid >> 4;    // row group (4 rows)

    const int lr  = tid >> 2;          // 0..63
    const int ld0 = (tid & 3) << 4;    // 0,16,32,48

    {
        const float* qb = qkv + ((size_t)(b * T_SEQ + q0 + lr)) * C3 + h * DH + ld0;
#pragma unroll
        for (int gg = 0; gg < 4; gg++) {
            float4 v = *(const float4*)(qb + gg * 4);
            int d = ld0 + gg * 4;
            Qs[d + 0][lr] = v.x * 0.125f;
            Qs[d + 1][lr] = v.y * 0.125f;
            Qs[d + 2][lr] = v.z * 0.125f;
            Qs[d + 3][lr] = v.w * 0.125f;
        }
    }

    float m[4], l[4], o[4][4];
#pragma unroll
    for (int i = 0; i < 4; i++) {
        m[i] = -1e30f; l[i] = 0.f;
#pragma unroll
        for (int c = 0; c < 4; c++) o[i][c] = 0.f;
    }

    for (int k0 = 0; k0 <= q0; k0 += 64) {
        __syncthreads();

        {
            const float* kb = qkv + ((size_t)(b * T_SEQ + k0 + lr)) * C3
                              + C_DIM + h * DH + ld0;
            const float* vb = qkv + ((size_t)(b * T_SEQ + k0 + lr)) * C3
                              + 2 * C_DIM + h * DH + ld0;
#pragma unroll
            for (int gg = 0; gg < 4; gg++) {
                float4 kv = *(const float4*)(kb + gg * 4);
                int d = ld0 + gg * 4;
                Ks[d + 0][lr] = kv.x;
                Ks[d + 1][lr] = kv.y;
                Ks[d + 2][lr] = kv.z;
                Ks[d + 3][lr] = kv.w;
                *(float4*)&Vs[lr][d] = *(const float4*)(vb + gg * 4);
            }
        }
        __syncthreads();

        float s[4][4];
#pragma unroll
        for (int i = 0; i < 4; i++)
#pragma unroll
            for (int j = 0; j < 4; j++) s[i][j] = 0.f;

#pragma unroll 8
        for (int d = 0; d < 64; d++) {
            float4 aq = *(const float4*)&Qs[d][ty * 4];
            float4 bk = *(const float4*)&Ks[d][tx * 4];
            float a[4] = {aq.x, aq.y, aq.z, aq.w};
            float bb[4] = {bk.x, bk.y, bk.z, bk.w};
#pragma unroll
            for (int i = 0; i < 4; i++)
#pragma unroll
                for (int j = 0; j < 4; j++)
                    s[i][j] = fmaf(a[i], bb[j], s[i][j]);
        }

        if (k0 == q0) {
#pragma unroll
            for (int i = 0; i < 4; i++)
#pragma unroll
                for (int j = 0; j < 4; j++)
                    if (tx * 4 + j > ty * 4 + i) s[i][j] = -1e30f;
        }

#pragma unroll
        for (int i = 0; i < 4; i++) {
            float mx = fmaxf(fmaxf(s[i][0], s[i][1]), fmaxf(s[i][2], s[i][3]));
#pragma unroll
            for (int off = 1; off < 16; off <<= 1)
                mx = fmaxf(mx, __shfl_xor_sync(0xffffffffu, mx, off));
            float mn = fmaxf(m[i], mx);
            float f  = __expf(m[i] - mn);
            float p0 = __expf(s[i][0] - mn);
            float p1 = __expf(s[i][1] - mn);
            float p2 = __expf(s[i][2] - mn);
            float p3 = __expf(s[i][3] - mn);
            float rs = p0 + p1 + p2 + p3;
#pragma unroll
            for (int off = 1; off < 16; off <<= 1)
                rs += __shfl_xor_sync(0xffffffffu, rs, off);
            l[i] = l[i] * f + rs;
            m[i] = mn;
#pragma unroll
            for (int c = 0; c < 4; c++) o[i][c] *= f;
            *(float4*)&Ps[ty * 4 + i][tx * 4] = make_float4(p0, p1, p2, p3);
        }
        __syncthreads();

#pragma unroll 8
        for (int j = 0; j < 64; j++) {
            float4 v = *(const float4*)&Vs[j][tx * 4];
#pragma unroll
            for (int i = 0; i < 4; i++) {
                float a = Ps[ty * 4 + i][j];
                o[i][0] = fmaf(a, v.x, o[i][0]);
                o[i][1] = fmaf(a, v.y, o[i][1]);
                o[i][2] = fmaf(a, v.z, o[i][2]);
                o[i][3] = fmaf(a, v.w, o[i][3]);
            }
        }
    }

#pragma unroll
    for (int i = 0; i < 4; i++) {
        float inv = 1.f / l[i];
        float4 v = make_float4(o[i][0] * inv, o[i][1] * inv,
                               o[i][2] * inv, o[i][3] * inv);
        size_t row = (size_t)(b * T_SEQ + q0 + ty * 4 + i);
        *(float4*)(y + row * C_DIM + h * DH + tx * 4) = v;
    }
}

// ---------------------------------------------------------------------------
extern "C" void kernel_launch(void* const* d_in, const int* in_sizes, int n_in,
                              void* d_out, int out_size)
{
    const float* x     = (const float*)d_in[0];
    const float* Wqkv  = (const float*)d_in[1];
    const float* bqkv  = (const float*)d_in[2];
    const float* Wproj = (const float*)d_in[3];
    const float* bproj = (const float*)d_in[4];
    float* out = (float*)d_out;

    float *qkv, *y;
    cudaGetSymbolAddress((void**)&qkv, g_qkv);
    cudaGetSymbolAddress((void**)&y, g_y);

    const int attn_smem = (4096 * 3 + 64 * 68) * sizeof(float);  // 66560 B
    cudaFuncSetAttribute(attn_kernel,
                         cudaFuncAttributeMaxDynamicSharedMemorySize, attn_smem);

    // 1) QKV projection (tensor cores, TF32)
    tf32_gemm_bias<<<dim3(C3 / TBN, M_ROWS / TBM), 256>>>(
        x, Wqkv, bqkv, qkv, M_ROWS, C3, C_DIM);

    // 2) causal attention
    attn_kernel<<<dim3(T_SEQ / 64, NH, B_SZ), 256, attn_smem>>>(qkv, y);

    // 3) output projection (tensor cores, TF32)
    tf32_gemm_bias<<<dim3(C_DIM / TBN, M_ROWS / TBM), 256>>>(
        y, Wproj, bproj, out, M_ROWS, C_DIM, C_DIM);
}

// round 5
// speedup vs baseline: 1.9703x; 1.2644x over previous
#include <cuda_runtime.h>
#include <math.h>
#include <stdint.h>

// Shapes (fixed by the problem)
#define B_SZ   16
#define T_SEQ  1024
#define C_DIM  768
#define NH     12
#define DH     64
#define C3     2304       // 3*C
#define M_ROWS 16384      // B*T

// Scratch buffers (no cudaMalloc allowed)
__device__ float g_qkv[(size_t)M_ROWS * C3];   // [B*T, 3C]
__device__ float g_y[(size_t)M_ROWS * C_DIM];  // [B*T, C]

// ---------------------------------------------------------------------------
// Shared helpers
// ---------------------------------------------------------------------------
__device__ __forceinline__ uint32_t f2tf32(float x) {
    uint32_t y;
    asm volatile("cvt.rna.tf32.f32 %0, %1;" : "=r"(y) : "f"(x));
    return y;
}

__device__ __forceinline__ void mma_tf32(float* c, const uint32_t* a, const uint32_t* b) {
    asm volatile(
        "mma.sync.aligned.m16n8k8.row.col.f32.tf32.tf32.f32 "
        "{%0,%1,%2,%3}, {%4,%5,%6,%7}, {%8,%9}, {%0,%1,%2,%3};"
        : "+f"(c[0]), "+f"(c[1]), "+f"(c[2]), "+f"(c[3])
        : "r"(a[0]), "r"(a[1]), "r"(a[2]), "r"(a[3]), "r"(b[0]), "r"(b[1]));
}

// ---------------------------------------------------------------------------
// TF32 tensor-core GEMM (unchanged from R2 — known good)
// ---------------------------------------------------------------------------
#define TBM 128
#define TBN 128
#define TBK 32
#define APAD 4
#define BPAD 8

__global__ __launch_bounds__(256) void tf32_gemm_bias(
    const float* __restrict__ A, const float* __restrict__ B,
    const float* __restrict__ bias, float* __restrict__ C,
    int M, int N, int K)
{
    __shared__ uint32_t As[TBM][TBK + APAD];
    __shared__ uint32_t Bs[TBK][TBN + BPAD];

    const int tid  = threadIdx.x;
    const int wid  = tid >> 5;
    const int lane = tid & 31;
    const int wm   = wid & 1;
    const int wn   = wid >> 1;
    const int g    = lane >> 2;
    const int tg   = lane & 3;

    const int ar = tid >> 1;
    const int ac = (tid & 1) * 16;
    const int br = tid >> 3;
    const int bc = (tid & 7) * 16;

    const float* Ag = A + (size_t)(blockIdx.y * TBM + ar) * K + ac;
    const float* Bg = B + (size_t)br * N + blockIdx.x * TBN + bc;

    float acc[4][4][4];
#pragma unroll
    for (int mt = 0; mt < 4; mt++)
#pragma unroll
        for (int nt = 0; nt < 4; nt++)
#pragma unroll
            for (int c = 0; c < 4; c++) acc[mt][nt][c] = 0.f;

    float4 pa[4], pb[4];
#pragma unroll
    for (int j = 0; j < 4; j++) {
        pa[j] = *(const float4*)(Ag + 4 * j);
        pb[j] = *(const float4*)(Bg + 4 * j);
    }
#pragma unroll
    for (int j = 0; j < 4; j++) {
        uint32_t* as = &As[ar][ac + 4 * j];
        as[0] = f2tf32(pa[j].x); as[1] = f2tf32(pa[j].y);
        as[2] = f2tf32(pa[j].z); as[3] = f2tf32(pa[j].w);
        uint32_t* bs = &Bs[br][bc + 4 * j];
        bs[0] = f2tf32(pb[j].x); bs[1] = f2tf32(pb[j].y);
        bs[2] = f2tf32(pb[j].z); bs[3] = f2tf32(pb[j].w);
    }
    __syncthreads();

    for (int k0 = 0; k0 < K; k0 += TBK) {
        const bool has_next = (k0 + TBK) < K;
        if (has_next) {
#pragma unroll
            for (int j = 0; j < 4; j++) {
                pa[j] = *(const float4*)(Ag + (k0 + TBK) + 4 * j);
                pb[j] = *(const float4*)(Bg + (size_t)(k0 + TBK) * N + 4 * j);
            }
        }

#pragma unroll
        for (int ks = 0; ks < 4; ks++) {
            uint32_t af[4][4], bf[4][2];
#pragma unroll
            for (int mt = 0; mt < 4; mt++) {
                const int am = wm * 64 + mt * 16;
                const int kk = ks * 8 + tg;
                af[mt][0] = As[am + g    ][kk    ];
                af[mt][1] = As[am + g + 8][kk    ];
                af[mt][2] = As[am + g    ][kk + 4];
                af[mt][3] = As[am + g + 8][kk + 4];
            }
#pragma unroll
            for (int nt = 0; nt < 4; nt++) {
                const int bn = wn * 32 + nt * 8 + g;
                const int kk = ks * 8 + tg;
                bf[nt][0] = Bs[kk    ][bn];
                bf[nt][1] = Bs[kk + 4][bn];
            }
#pragma unroll
            for (int mt = 0; mt < 4; mt++)
#pragma unroll
                for (int nt = 0; nt < 4; nt++)
                    mma_tf32(acc[mt][nt], af[mt], bf[nt]);
        }

        __syncthreads();
        if (has_next) {
#pragma unroll
            for (int j = 0; j < 4; j++) {
                uint32_t* as = &As[ar][ac + 4 * j];
                as[0] = f2tf32(pa[j].x); as[1] = f2tf32(pa[j].y);
                as[2] = f2tf32(pa[j].z); as[3] = f2tf32(pa[j].w);
                uint32_t* bs = &Bs[br][bc + 4 * j];
                bs[0] = f2tf32(pb[j].x); bs[1] = f2tf32(pb[j].y);
                bs[2] = f2tf32(pb[j].z); bs[3] = f2tf32(pb[j].w);
            }
            __syncthreads();
        }
    }

    const int crow0 = blockIdx.y * TBM + wm * 64;
    const int ccol0 = blockIdx.x * TBN + wn * 32;
#pragma unroll
    for (int mt = 0; mt < 4; mt++) {
#pragma unroll
        for (int nt = 0; nt < 4; nt++) {
            const int row = crow0 + mt * 16 + g;
            const int col = ccol0 + nt * 8 + 2 * tg;
            const float b0 = bias[col], b1 = bias[col + 1];
            float2 v0 = make_float2(acc[mt][nt][0] + b0, acc[mt][nt][1] + b1);
            float2 v1 = make_float2(acc[mt][nt][2] + b0, acc[mt][nt][3] + b1);
            *(float2*)(C + (size_t)row * N + col)       = v0;
            *(float2*)(C + (size_t)(row + 8) * N + col) = v1;
        }
    }
}

// ---------------------------------------------------------------------------
// Flash-attention on mma.sync TF32.
// One block per (q_tile=64, head, batch). 128 threads = 4 warps.
// Warp w owns S/O rows 16w..16w+15. Q pre-scaled by 1/sqrt(D)=0.125.
// Smem tiles [64][68] (tf32 bits): Qs, Ks (row=token, col=d), Vs (row=token,
// col=d), Ps (row=q, col=key; reused as float O-staging at the end).
// All fragment LDS patterns are bank-conflict-free with the 68-word pitch.
// ---------------------------------------------------------------------------
#define AP 68
#define ATTN_SMEM (4 * 64 * AP * 4)   // 69632 B

__global__ __launch_bounds__(128) void attn_mma_kernel(
    const float* __restrict__ qkv, float* __restrict__ y)
{
    extern __shared__ uint32_t smu[];
    uint32_t* Qs = smu;                 // [64][AP]
    uint32_t* Ks = smu + 64 * AP;       // [64][AP]
    uint32_t* Vs = smu + 2 * 64 * AP;   // [64][AP]
    uint32_t* Ps = smu + 3 * 64 * AP;   // [64][AP]

    const int q0 = blockIdx.x * 64;
    const int h  = blockIdx.y;
    const int b  = blockIdx.z;

    const int tid  = threadIdx.x;
    const int w    = tid >> 5;
    const int lane = tid & 31;
    const int g    = lane >> 2;
    const int tg   = lane & 3;

    // loader mapping: warp-contiguous rows, conflict-free STS.128
    const int lr  = tid & 63;            // row 0..63
    const int lc0 = (tid >> 6) * 32;     // col 0 or 32

    // ---- load Q tile (scaled, tf32) ----
    {
        const float* qb = qkv + ((size_t)(b * T_SEQ + q0 + lr)) * C3 + h * DH + lc0;
        uint32_t* dst = Qs + lr * AP + lc0;
#pragma unroll
        for (int j = 0; j < 8; j++) {
            float4 v = *(const float4*)(qb + 4 * j);
            dst[4 * j + 0] = f2tf32(v.x * 0.125f);
            dst[4 * j + 1] = f2tf32(v.y * 0.125f);
            dst[4 * j + 2] = f2tf32(v.z * 0.125f);
            dst[4 * j + 3] = f2tf32(v.w * 0.125f);
        }
    }

    // per-thread softmax state: rows r0 = 16w+g, r1 = 16w+g+8
    float m0 = -1e30f, m1 = -1e30f, l0 = 0.f, l1 = 0.f;
    float o[8][4];
#pragma unroll
    for (int nt = 0; nt < 8; nt++)
#pragma unroll
        for (int c = 0; c < 4; c++) o[nt][c] = 0.f;

    const int row_g = 16 * w + g;        // local q row (first of pair)

    for (int k0 = 0; k0 <= q0; k0 += 64) {
        __syncthreads();
        // ---- load K and V tiles (tf32) ----
        {
            const float* kb = qkv + ((size_t)(b * T_SEQ + k0 + lr)) * C3 + C_DIM + h * DH + lc0;
            const float* vb = qkv + ((size_t)(b * T_SEQ + k0 + lr)) * C3 + 2 * C_DIM + h * DH + lc0;
            uint32_t* kd = Ks + lr * AP + lc0;
            uint32_t* vd = Vs + lr * AP + lc0;
#pragma unroll
            for (int j = 0; j < 8; j++) {
                float4 kv = *(const float4*)(kb + 4 * j);
                kd[4 * j + 0] = f2tf32(kv.x);
                kd[4 * j + 1] = f2tf32(kv.y);
                kd[4 * j + 2] = f2tf32(kv.z);
                kd[4 * j + 3] = f2tf32(kv.w);
                float4 vv = *(const float4*)(vb + 4 * j);
                vd[4 * j + 0] = f2tf32(vv.x);
                vd[4 * j + 1] = f2tf32(vv.y);
                vd[4 * j + 2] = f2tf32(vv.z);
                vd[4 * j + 3] = f2tf32(vv.w);
            }
        }
        __syncthreads();

        // ---- S = Q @ K^T : warp strip 16 x 64 ----
        float s[8][4];
#pragma unroll
        for (int nt = 0; nt < 8; nt++)
#pragma unroll
            for (int c = 0; c < 4; c++) s[nt][c] = 0.f;

#pragma unroll
        for (int ks = 0; ks < 8; ks++) {
            const int kk = ks * 8 + tg;
            uint32_t a[4];
            a[0] = Qs[(row_g    ) * AP + kk    ];
            a[1] = Qs[(row_g + 8) * AP + kk    ];
            a[2] = Qs[(row_g    ) * AP + kk + 4];
            a[3] = Qs[(row_g + 8) * AP + kk + 4];
#pragma unroll
            for (int nt = 0; nt < 8; nt++) {
                uint32_t bb[2];
                bb[0] = Ks[(nt * 8 + g) * AP + kk    ];
                bb[1] = Ks[(nt * 8 + g) * AP + kk + 4];
                mma_tf32(s[nt], a, bb);
            }
        }

        // ---- causal mask (diagonal tile only) ----
        if (k0 == q0) {
#pragma unroll
            for (int nt = 0; nt < 8; nt++) {
                const int c0 = nt * 8 + 2 * tg;
                if (c0     > row_g    ) s[nt][0] = -1e30f;
                if (c0 + 1 > row_g    ) s[nt][1] = -1e30f;
                if (c0     > row_g + 8) s[nt][2] = -1e30f;
                if (c0 + 1 > row_g + 8) s[nt][3] = -1e30f;
            }
        }

        // ---- online softmax (2 rows/thread, quad reductions) ----
        float mx0 = -1e30f, mx1 = -1e30f;
#pragma unroll
        for (int nt = 0; nt < 8; nt++) {
            mx0 = fmaxf(mx0, fmaxf(s[nt][0], s[nt][1]));
            mx1 = fmaxf(mx1, fmaxf(s[nt][2], s[nt][3]));
        }
        mx0 = fmaxf(mx0, __shfl_xor_sync(0xffffffffu, mx0, 1));
        mx0 = fmaxf(mx0, __shfl_xor_sync(0xffffffffu, mx0, 2));
        mx1 = fmaxf(mx1, __shfl_xor_sync(0xffffffffu, mx1, 1));
        mx1 = fmaxf(mx1, __shfl_xor_sync(0xffffffffu, mx1, 2));

        const float mn0 = fmaxf(m0, mx0);
        const float mn1 = fmaxf(m1, mx1);
        const float f0  = __expf(m0 - mn0);
        const float f1  = __expf(m1 - mn1);

        float sum0 = 0.f, sum1 = 0.f;
#pragma unroll
        for (int nt = 0; nt < 8; nt++) {
            float p0 = __expf(s[nt][0] - mn0);
            float p1 = __expf(s[nt][1] - mn0);
            float p2 = __expf(s[nt][2] - mn1);
            float p3 = __expf(s[nt][3] - mn1);
            sum0 += p0 + p1;
            sum1 += p2 + p3;
            // stage P (tf32) — warp-local rows
            uint32_t* p0d = Ps + (row_g    ) * AP + nt * 8 + 2 * tg;
            uint32_t* p1d = Ps + (row_g + 8) * AP + nt * 8 + 2 * tg;
            p0d[0] = f2tf32(p0); p0d[1] = f2tf32(p1);
            p1d[0] = f2tf32(p2); p1d[1] = f2tf32(p3);
        }
        sum0 += __shfl_xor_sync(0xffffffffu, sum0, 1);
        sum0 += __shfl_xor_sync(0xffffffffu, sum0, 2);
        sum1 += __shfl_xor_sync(0xffffffffu, sum1, 1);
        sum1 += __shfl_xor_sync(0xffffffffu, sum1, 2);

        l0 = l0 * f0 + sum0;  m0 = mn0;
        l1 = l1 * f1 + sum1;  m1 = mn1;
#pragma unroll
        for (int nt = 0; nt < 8; nt++) {
            o[nt][0] *= f0; o[nt][1] *= f0;
            o[nt][2] *= f1; o[nt][3] *= f1;
        }
        __syncwarp();

        // ---- O += P @ V ----
#pragma unroll
        for (int ks = 0; ks < 8; ks++) {
            const int kk = ks * 8 + tg;
            uint32_t a[4];
            a[0] = Ps[(row_g    ) * AP + kk    ];
            a[1] = Ps[(row_g + 8) * AP + kk    ];
            a[2] = Ps[(row_g    ) * AP + kk + 4];
            a[3] = Ps[(row_g + 8) * AP + kk + 4];
#pragma unroll
            for (int nt = 0; nt < 8; nt++) {
                uint32_t bb[2];
                bb[0] = Vs[(kk    ) * AP + nt * 8 + g];
                bb[1] = Vs[(kk + 4) * AP + nt * 8 + g];
                mma_tf32(o[nt], a, bb);
            }
        }
    }

    // ---- normalize, stage to smem, coalesced write ----
    __syncthreads();   // all warps done with Ps as tf32 P
    float* Of = (float*)Ps;
    const float inv0 = 1.f / l0;
    const float inv1 = 1.f / l1;
#pragma unroll
    for (int nt = 0; nt < 8; nt++) {
        float* d0 = Of + (row_g    ) * AP + nt * 8 + 2 * tg;
        float* d1 = Of + (row_g + 8) * AP + nt * 8 + 2 * tg;
        d0[0] = o[nt][0] * inv0; d0[1] = o[nt][1] * inv0;
        d1[0] = o[nt][2] * inv1; d1[1] = o[nt][3] * inv1;
    }
    __syncthreads();
    {
        const float* src = Of + lr * AP + lc0;
        float* dst = y + ((size_t)(b * T_SEQ + q0 + lr)) * C_DIM + h * DH + lc0;
#pragma unroll
        for (int j = 0; j < 8; j++)
            *(float4*)(dst + 4 * j) = *(const float4*)(src + 4 * j);
    }
}

// ---------------------------------------------------------------------------
extern "C" void kernel_launch(void* const* d_in, const int* in_sizes, int n_in,
                              void* d_out, int out_size)
{
    const float* x     = (const float*)d_in[0];
    const float* Wqkv  = (const float*)d_in[1];
    const float* bqkv  = (const float*)d_in[2];
    const float* Wproj = (const float*)d_in[3];
    const float* bproj = (const float*)d_in[4];
    float* out = (float*)d_out;

    float *qkv, *y;
    cudaGetSymbolAddress((void**)&qkv, g_qkv);
    cudaGetSymbolAddress((void**)&y, g_y);

    cudaFuncSetAttribute(attn_mma_kernel,
                         cudaFuncAttributeMaxDynamicSharedMemorySize, ATTN_SMEM);

    // 1) QKV projection (tensor cores, TF32)
    tf32_gemm_bias<<<dim3(C3 / TBN, M_ROWS / TBM), 256>>>(
        x, Wqkv, bqkv, qkv, M_ROWS, C3, C_DIM);

    // 2) causal attention (tensor cores, TF32)
    attn_mma_kernel<<<dim3(T_SEQ / 64, NH, B_SZ), 128, ATTN_SMEM>>>(qkv, y);

    // 3) output projection (tensor cores, TF32)
    tf32_gemm_bias<<<dim3(C_DIM / TBN, M_ROWS / TBM), 256>>>(
        y, Wproj, bproj, out, M_ROWS, C_DIM, C_DIM);
}

// round 9
// speedup vs baseline: 3.2702x; 1.6598x over previous
#include <cuda_runtime.h>
#include <math.h>
#include <stdint.h>

// Shapes (fixed by the problem)
#define B_SZ   16
#define T_SEQ  1024
#define C_DIM  768
#define NH     12
#define DH     64
#define C3     2304       // 3*C
#define M_ROWS 16384      // B*T

// Scratch buffers (no cudaMalloc allowed)
__device__ float g_qkv[(size_t)M_ROWS * C3];   // [B*T, 3C]
__device__ float g_y[(size_t)M_ROWS * C_DIM];  // [B*T, C]

// ---------------------------------------------------------------------------
// Shared helpers
// ---------------------------------------------------------------------------
__device__ __forceinline__ uint32_t f2tf32(float x) {
    uint32_t y;
    asm volatile("cvt.rna.tf32.f32 %0, %1;" : "=r"(y) : "f"(x));
    return y;
}
__device__ __forceinline__ uint4 cvt4(float4 v) {
    return make_uint4(f2tf32(v.x), f2tf32(v.y), f2tf32(v.z), f2tf32(v.w));
}
__device__ __forceinline__ uint4 cvt4s(float4 v, float s) {
    return make_uint4(f2tf32(v.x * s), f2tf32(v.y * s), f2tf32(v.z * s), f2tf32(v.w * s));
}

__device__ __forceinline__ void mma_tf32(float* c, const uint32_t* a, const uint32_t* b) {
    asm volatile(
        "mma.sync.aligned.m16n8k8.row.col.f32.tf32.tf32.f32 "
        "{%0,%1,%2,%3}, {%4,%5,%6,%7}, {%8,%9}, {%0,%1,%2,%3};"
        : "+f"(c[0]), "+f"(c[1]), "+f"(c[2]), "+f"(c[3])
        : "r"(a[0]), "r"(a[1]), "r"(a[2]), "r"(a[3]), "r"(b[0]), "r"(b[1]));
}

// ---------------------------------------------------------------------------
// TF32 GEMM v3: C = A[M,K] @ B[K,N] + bias[N], row-major.
// CTA tile 256x128, 8 warps in 4x2, warp tile 64x64 (mt=4 x nt=8), BK=32.
// Smem reads per mma: A 512/8 + B 256/4 = 128 B  (was 192).
// Dynamic smem: As[256][36] then Bs[32][136] = 54272 B total.
// ---------------------------------------------------------------------------
#define GBM 256
#define GBN 128
#define GBK 32
#define GAP 36    // As pitch (words)
#define GBP 136   // Bs pitch (words)
#define GEMM_SMEM ((GBM * GAP + GBK * GBP) * 4)   // 54272 B

__global__ __launch_bounds__(256, 1) void tf32_gemm_bias(
    const float* __restrict__ A, const float* __restrict__ B,
    const float* __restrict__ bias, float* __restrict__ C,
    int M, int N, int K)
{
    extern __shared__ uint32_t gsm[];
    uint32_t* As = gsm;                 // [GBM][GAP]
    uint32_t* Bs = gsm + GBM * GAP;     // [GBK][GBP]

    const int tid  = threadIdx.x;
    const int wid  = tid >> 5;
    const int lane = tid & 31;
    const int wm   = wid >> 1;      // 0..3  (64-row strip)
    const int wn   = wid & 1;       // 0..1  (64-col strip)
    const int g    = lane >> 2;     // 0..7
    const int tg   = lane & 3;      // 0..3

    // A loader: rows ar+32i (i=0..7), cols ac..ac+3
    const int ar = tid >> 3;            // 0..31
    const int ac = (tid & 7) * 4;       // 0..28
    // B loader: k-row bkr, cols bc+32j (j=0..3)
    const int bkr = tid >> 3;           // 0..31
    const int bc  = (tid & 7) * 4;      // 0..28

    const float* Ag = A + (size_t)(blockIdx.y * GBM + ar) * K + ac;
    const float* Bg = B + (size_t)bkr * N + blockIdx.x * GBN + bc;

    float acc[4][8][4];
#pragma unroll
    for (int mt = 0; mt < 4; mt++)
#pragma unroll
        for (int nt = 0; nt < 8; nt++)
#pragma unroll
            for (int c = 0; c < 4; c++) acc[mt][nt][c] = 0.f;

    float4 pa[8], pb[4];
#pragma unroll
    for (int i = 0; i < 8; i++) pa[i] = *(const float4*)(Ag + (size_t)(32 * i) * K);
#pragma unroll
    for (int j = 0; j < 4; j++) pb[j] = *(const float4*)(Bg + 32 * j);
#pragma unroll
    for (int i = 0; i < 8; i++) *(uint4*)&As[(ar + 32 * i) * GAP + ac] = cvt4(pa[i]);
#pragma unroll
    for (int j = 0; j < 4; j++) *(uint4*)&Bs[bkr * GBP + bc + 32 * j] = cvt4(pb[j]);
    __syncthreads();

    for (int k0 = 0; k0 < K; k0 += GBK) {
        const bool has_next = (k0 + GBK) < K;
        if (has_next) {
#pragma unroll
            for (int i = 0; i < 8; i++)
                pa[i] = *(const float4*)(Ag + (size_t)(32 * i) * K + k0 + GBK);
#pragma unroll
            for (int j = 0; j < 4; j++)
                pb[j] = *(const float4*)(Bg + (size_t)(k0 + GBK) * N + 32 * j);
        }

#pragma unroll
        for (int ks = 0; ks < 4; ks++) {
            const int kk = ks * 8 + tg;
            uint32_t af[4][4], bf[8][2];
#pragma unroll
            for (int mt = 0; mt < 4; mt++) {
                const int am = wm * 64 + mt * 16;
                af[mt][0] = As[(am + g    ) * GAP + kk    ];
                af[mt][1] = As[(am + g + 8) * GAP + kk    ];
                af[mt][2] = As[(am + g    ) * GAP + kk + 4];
                af[mt][3] = As[(am + g + 8) * GAP + kk + 4];
            }
#pragma unroll
            for (int nt = 0; nt < 8; nt++) {
                const int bn = wn * 64 + nt * 8 + g;
                bf[nt][0] = Bs[(kk    ) * GBP + bn];
                bf[nt][1] = Bs[(kk + 4) * GBP + bn];
            }
#pragma unroll
            for (int mt = 0; mt < 4; mt++)
#pragma unroll
                for (int nt = 0; nt < 8; nt++)
                    mma_tf32(acc[mt][nt], af[mt], bf[nt]);
        }

        __syncthreads();
        if (has_next) {
#pragma unroll
            for (int i = 0; i < 8; i++) *(uint4*)&As[(ar + 32 * i) * GAP + ac] = cvt4(pa[i]);
#pragma unroll
            for (int j = 0; j < 4; j++) *(uint4*)&Bs[bkr * GBP + bc + 32 * j] = cvt4(pb[j]);
            __syncthreads();
        }
    }

    const int crow0 = blockIdx.y * GBM + wm * 64;
    const int ccol0 = blockIdx.x * GBN + wn * 64;
#pragma unroll
    for (int mt = 0; mt < 4; mt++) {
#pragma unroll
        for (int nt = 0; nt < 8; nt++) {
            const int row = crow0 + mt * 16 + g;
            const int col = ccol0 + nt * 8 + 2 * tg;
            const float b0 = bias[col], b1 = bias[col + 1];
            float2 v0 = make_float2(acc[mt][nt][0] + b0, acc[mt][nt][1] + b1);
            float2 v1 = make_float2(acc[mt][nt][2] + b0, acc[mt][nt][3] + b1);
            *(float2*)(C + (size_t)row * N + col)       = v0;
            *(float2*)(C + (size_t)(row + 8) * N + col) = v1;
        }
    }
}

// ---------------------------------------------------------------------------
// Flash-attention v2 on mma.sync TF32.
// q-tile 128, 4 warps; warp w owns rows 32w..32w+31 (mt=2 x 16-row).
// k-tile 64. Smem per mma: Q 512/8 + K 256/2 = 192 B (was 320).
// Smem (uint32/float, pitch 68): Qs[128], Ks[64], Vs[64], Ps[128] rows.
// ---------------------------------------------------------------------------
#define AP 68
#define ATTN_SMEM ((128 + 64 + 64 + 128) * AP * 4)   // 104448 B

__global__ __launch_bounds__(128) void attn_mma_kernel(
    const float* __restrict__ qkv, float* __restrict__ y)
{
    extern __shared__ uint32_t smu[];
    uint32_t* Qs = smu;                   // [128][AP]
    uint32_t* Ks = smu + 128 * AP;        // [64][AP]
    uint32_t* Vs = smu + 192 * AP;        // [64][AP]
    uint32_t* Ps = smu + 256 * AP;        // [128][AP]

    const int q0 = blockIdx.x * 128;
    const int h  = blockIdx.y;
    const int b  = blockIdx.z;

    const int tid  = threadIdx.x;
    const int w    = tid >> 5;
    const int lane = tid & 31;
    const int g    = lane >> 2;
    const int tg   = lane & 3;

    // loader mapping: 2 threads per row; 16-float segments at colb and colb+32
    const int lr   = tid >> 1;            // 0..63
    const int colb = (tid & 1) * 16;      // 0 or 16

    // ---- load Q tile (128 rows, scaled, tf32) ----
#pragma unroll
    for (int rh = 0; rh < 2; rh++) {
        const int rr = lr + 64 * rh;
        const float* src = qkv + ((size_t)(b * T_SEQ + q0 + rr)) * C3 + h * DH;
        uint32_t* dst = Qs + rr * AP;
#pragma unroll
        for (int hs = 0; hs < 2; hs++) {
            const int c0 = colb + 32 * hs;
#pragma unroll
            for (int j = 0; j < 4; j++)
                *(uint4*)(dst + c0 + 4 * j) = cvt4s(*(const float4*)(src + c0 + 4 * j), 0.125f);
        }
    }

    // softmax state: rows r(mt,0) = 32w+16mt+g, r(mt,1) = +8
    float m[2][2], l[2][2], o[2][8][4];
#pragma unroll
    for (int mt = 0; mt < 2; mt++) {
        m[mt][0] = -1e30f; m[mt][1] = -1e30f;
        l[mt][0] = 0.f;    l[mt][1] = 0.f;
#pragma unroll
        for (int nt = 0; nt < 8; nt++)
#pragma unroll
            for (int c = 0; c < 4; c++) o[mt][nt][c] = 0.f;
    }

    const int rowg0 = 32 * w + g;         // mt=0 base row
    const int kmax  = q0 + 64;

    for (int k0 = 0; k0 <= kmax; k0 += 64) {
        __syncthreads();
        // ---- load K and V tiles (64 rows, tf32) ----
        {
            const float* kb = qkv + ((size_t)(b * T_SEQ + k0 + lr)) * C3 + C_DIM + h * DH;
            const float* vb = qkv + ((size_t)(b * T_SEQ + k0 + lr)) * C3 + 2 * C_DIM + h * DH;
            uint32_t* kd = Ks + lr * AP;
            uint32_t* vd = Vs + lr * AP;
#pragma unroll
            for (int hs = 0; hs < 2; hs++) {
                const int c0 = colb + 32 * hs;
#pragma unroll
                for (int j = 0; j < 4; j++) {
                    *(uint4*)(kd + c0 + 4 * j) = cvt4(*(const float4*)(kb + c0 + 4 * j));
                    *(uint4*)(vd + c0 + 4 * j) = cvt4(*(const float4*)(vb + c0 + 4 * j));
                }
            }
        }
        __syncthreads();

        // ---- S = Q @ K^T : warp strip 32 x 64 ----
        float s[2][8][4];
#pragma unroll
        for (int mt = 0; mt < 2; mt++)
#pragma unroll
            for (int nt = 0; nt < 8; nt++)
#pragma unroll
                for (int c = 0; c < 4; c++) s[mt][nt][c] = 0.f;

#pragma unroll
        for (int ks = 0; ks < 8; ks++) {
            const int kk = ks * 8 + tg;
            uint32_t af[2][4];
#pragma unroll
            for (int mt = 0; mt < 2; mt++) {
                const int r = rowg0 + 16 * mt;
                af[mt][0] = Qs[(r    ) * AP + kk    ];
                af[mt][1] = Qs[(r + 8) * AP + kk    ];
                af[mt][2] = Qs[(r    ) * AP + kk + 4];
                af[mt][3] = Qs[(r + 8) * AP + kk + 4];
            }
#pragma unroll
            for (int nt = 0; nt < 8; nt++) {
                uint32_t bb[2];
                bb[0] = Ks[(nt * 8 + g) * AP + kk    ];
                bb[1] = Ks[(nt * 8 + g) * AP + kk + 4];
                mma_tf32(s[0][nt], af[0], bb);
                mma_tf32(s[1][nt], af[1], bb);
            }
        }

        // ---- causal mask (k0 >= q0 tiles) ----
        if (k0 >= q0) {
            const int dk = k0 - q0;
#pragma unroll
            for (int mt = 0; mt < 2; mt++) {
                const int r0 = rowg0 + 16 * mt;
#pragma unroll
                for (int nt = 0; nt < 8; nt++) {
                    const int c0 = nt * 8 + 2 * tg + dk;
                    if (c0     > r0    ) s[mt][nt][0] = -1e30f;
                    if (c0 + 1 > r0    ) s[mt][nt][1] = -1e30f;
                    if (c0     > r0 + 8) s[mt][nt][2] = -1e30f;
                    if (c0 + 1 > r0 + 8) s[mt][nt][3] = -1e30f;
                }
            }
        }

        // ---- online softmax (4 rows/thread, quad reductions) ----
#pragma unroll
        for (int mt = 0; mt < 2; mt++) {
            float mx0 = -1e30f, mx1 = -1e30f;
#pragma unroll
            for (int nt = 0; nt < 8; nt++) {
                mx0 = fmaxf(mx0, fmaxf(s[mt][nt][0], s[mt][nt][1]));
                mx1 = fmaxf(mx1, fmaxf(s[mt][nt][2], s[mt][nt][3]));
            }
            mx0 = fmaxf(mx0, __shfl_xor_sync(0xffffffffu, mx0, 1));
            mx0 = fmaxf(mx0, __shfl_xor_sync(0xffffffffu, mx0, 2));
            mx1 = fmaxf(mx1, __shfl_xor_sync(0xffffffffu, mx1, 1));
            mx1 = fmaxf(mx1, __shfl_xor_sync(0xffffffffu, mx1, 2));

            const float mn0 = fmaxf(m[mt][0], mx0);
            const float mn1 = fmaxf(m[mt][1], mx1);
            const float f0  = __expf(m[mt][0] - mn0);
            const float f1  = __expf(m[mt][1] - mn1);

            const int r0 = rowg0 + 16 * mt;
            float sum0 = 0.f, sum1 = 0.f;
#pragma unroll
            for (int nt = 0; nt < 8; nt++) {
                float p0 = __expf(s[mt][nt][0] - mn0);
                float p1 = __expf(s[mt][nt][1] - mn0);
                float p2 = __expf(s[mt][nt][2] - mn1);
                float p3 = __expf(s[mt][nt][3] - mn1);
                sum0 += p0 + p1;
                sum1 += p2 + p3;
                uint32_t* p0d = Ps + (r0    ) * AP + nt * 8 + 2 * tg;
                uint32_t* p1d = Ps + (r0 + 8) * AP + nt * 8 + 2 * tg;
                p0d[0] = f2tf32(p0); p0d[1] = f2tf32(p1);
                p1d[0] = f2tf32(p2); p1d[1] = f2tf32(p3);
            }
            sum0 += __shfl_xor_sync(0xffffffffu, sum0, 1);
            sum0 += __shfl_xor_sync(0xffffffffu, sum0, 2);
            sum1 += __shfl_xor_sync(0xffffffffu, sum1, 1);
            sum1 += __shfl_xor_sync(0xffffffffu, sum1, 2);

            l[mt][0] = l[mt][0] * f0 + sum0;  m[mt][0] = mn0;
            l[mt][1] = l[mt][1] * f1 + sum1;  m[mt][1] = mn1;
#pragma unroll
            for (int nt = 0; nt < 8; nt++) {
                o[mt][nt][0] *= f0; o[mt][nt][1] *= f0;
                o[mt][nt][2] *= f1; o[mt][nt][3] *= f1;
            }
        }
        __syncwarp();

        // ---- O += P @ V ----
#pragma unroll
        for (int ks = 0; ks < 8; ks++) {
            const int kk = ks * 8 + tg;
            uint32_t af[2][4];
#pragma unroll
            for (int mt = 0; mt < 2; mt++) {
                const int r = rowg0 + 16 * mt;
                af[mt][0] = Ps[(r    ) * AP + kk    ];
                af[mt][1] = Ps[(r + 8) * AP + kk    ];
                af[mt][2] = Ps[(r    ) * AP + kk + 4];
                af[mt][3] = Ps[(r + 8) * AP + kk + 4];
            }
#pragma unroll
            for (int nt = 0; nt < 8; nt++) {
                uint32_t bb[2];
                bb[0] = Vs[(kk    ) * AP + nt * 8 + g];
                bb[1] = Vs[(kk + 4) * AP + nt * 8 + g];
                mma_tf32(o[0][nt], af[0], bb);
                mma_tf32(o[1][nt], af[1], bb);
            }
        }
    }

    // ---- normalize, stage to smem (as float), coalesced write ----
    __syncthreads();
    float* Of = (float*)Ps;
#pragma unroll
    for (int mt = 0; mt < 2; mt++) {
        const int r0 = rowg0 + 16 * mt;
        const float inv0 = 1.f / l[mt][0];
        const float inv1 = 1.f / l[mt][1];
#pragma unroll
        for (int nt = 0; nt < 8; nt++) {
            float* d0 = Of + (r0    ) * AP + nt * 8 + 2 * tg;
            float* d1 = Of + (r0 + 8) * AP + nt * 8 + 2 * tg;
            d0[0] = o[mt][nt][0] * inv0; d0[1] = o[mt][nt][1] * inv0;
            d1[0] = o[mt][nt][2] * inv1; d1[1] = o[mt][nt][3] * inv1;
        }
    }
    __syncthreads();
#pragma unroll
    for (int rh = 0; rh < 2; rh++) {
        const int rr = lr + 64 * rh;
        const float* src = Of + rr * AP;
        float* dst = y + ((size_t)(b * T_SEQ + q0 + rr)) * C_DIM + h * DH;
#pragma unroll
        for (int hs = 0; hs < 2; hs++) {
            const int c0 = colb + 32 * hs;
#pragma unroll
            for (int j = 0; j < 4; j++)
                *(float4*)(dst + c0 + 4 * j) = *(const float4*)(src + c0 + 4 * j);
        }
    }
}

// ---------------------------------------------------------------------------
extern "C" void kernel_launch(void* const* d_in, const int* in_sizes, int n_in,
                              void* d_out, int out_size)
{
    const float* x     = (const float*)d_in[0];
    const float* Wqkv  = (const float*)d_in[1];
    const float* bqkv  = (const float*)d_in[2];
    const float* Wproj = (const float*)d_in[3];
    const float* bproj = (const float*)d_in[4];
    float* out = (float*)d_out;

    float *qkv, *y;
    cudaGetSymbolAddress((void**)&qkv, g_qkv);
    cudaGetSymbolAddress((void**)&y, g_y);

    cudaFuncSetAttribute(tf32_gemm_bias,
                         cudaFuncAttributeMaxDynamicSharedMemorySize, GEMM_SMEM);
    cudaFuncSetAttribute(attn_mma_kernel,
                         cudaFuncAttributeMaxDynamicSharedMemorySize, ATTN_SMEM);

    // 1) QKV projection (tensor cores, TF32)
    tf32_gemm_bias<<<dim3(C3 / GBN, M_ROWS / GBM), 256, GEMM_SMEM>>>(
        x, Wqkv, bqkv, qkv, M_ROWS, C3, C_DIM);

    // 2) causal attention (tensor cores, TF32)
    attn_mma_kernel<<<dim3(T_SEQ / 128, NH, B_SZ), 128, ATTN_SMEM>>>(qkv, y);

    // 3) output projection (tensor cores, TF32)
    tf32_gemm_bias<<<dim3(C_DIM / GBN, M_ROWS / GBM), 256, GEMM_SMEM>>>(
        y, Wproj, bproj, out, M_ROWS, C_DIM, C_DIM);
}